// round 5
// baseline (speedup 1.0000x reference)
#include <cuda_runtime.h>

// Problem constants
#define NN 512
#define KK 17
#define WW 48
#define HH 64
#define NK (NN * KK)                       // 8704
#define HMSZ (HH * WW)                     // 3072
#define TOTAL ((double)NN * KK * HH * WW)  // 26738688

__device__ double g_acc;          // zero-initialized; reset by last block each run
__device__ unsigned int g_cnt;    // ditto

__global__ __launch_bounds__(256) void reg2hm_loss_kernel(
    const float* __restrict__ pred,      // [N,K,2]
    const float* __restrict__ sigma,     // [N,K,2]
    const float* __restrict__ teacher,   // [N,K,H,W]
    const float* __restrict__ twgt,      // [N,K,1]
    float* __restrict__ out)             // [1]
{
    const int nk  = blockIdx.x;          // 0..NK-1
    const int tid = threadIdx.x;

    // ---- Issue ALL global loads first (no barrier above these) ----
    // 3 coalesced float4 streaming loads per thread (768 float4 per block).
    const float4* tp = reinterpret_cast<const float4*>(teacher + (size_t)nk * HMSZ);
    const float4 t0 = tp[tid];
    const float4 t1 = tp[tid + 256];
    const float4 t2 = tp[tid + 512];

    // Uniform param loads (same address per warp -> broadcast).
    const float mux = pred[nk * 2 + 0] * (float)WW;
    const float muy = pred[nk * 2 + 1] * (float)HH;
    const float sx  = sigma[nk * 2 + 0];
    const float sy  = sigma[nk * 2 + 1];
    const float twv = twgt[nk];

    const float mask = ((mux - 3.0f * sx < (float)WW) &&
                        (muy - 3.0f * sy < (float)HH) &&
                        (mux + 3.0f * sx + 1.0f >= 0.0f) &&
                        (muy + 3.0f * sy + 1.0f >= 0.0f)) ? 1.0f : 0.0f;
    const float tw   = twv * mask;
    const float coef = tw * tw;          // zero whenever mask==0
    const float invx = 1.0f / (sx * sx + 1e-9f);
    const float invy = 1.0f / (sy * sy + 1e-9f);

    __shared__ float ex[WW];
    __shared__ float ey[HH];
    __shared__ float s_warp[8];

    if (tid < WW) {
        float d = (float)tid - mux;
        ex[tid] = __expf(-0.5f * d * d * invx);
    } else if (tid >= 64 && tid < 64 + HH) {
        int h = tid - 64;
        float d = (float)h - muy;
        ey[h] = __expf(-0.5f * d * d * invy);
    }
    __syncthreads();

    // quad index q in [0,768): row h = q/12 (a float4 never crosses a row, W=48)
    float sum;
    {
        int q = tid;
        int h = q / 12, w = (q % 12) * 4;
        float eyh = ey[h];
        float d0 = ex[w + 0] * eyh - t0.x;
        float d1 = ex[w + 1] * eyh - t0.y;
        float d2 = ex[w + 2] * eyh - t0.z;
        float d3 = ex[w + 3] * eyh - t0.w;
        sum = d0 * d0 + d1 * d1 + d2 * d2 + d3 * d3;
    }
    {
        int q = tid + 256;
        int h = q / 12, w = (q % 12) * 4;
        float eyh = ey[h];
        float d0 = ex[w + 0] * eyh - t1.x;
        float d1 = ex[w + 1] * eyh - t1.y;
        float d2 = ex[w + 2] * eyh - t1.z;
        float d3 = ex[w + 3] * eyh - t1.w;
        sum += d0 * d0 + d1 * d1 + d2 * d2 + d3 * d3;
    }
    {
        int q = tid + 512;
        int h = q / 12, w = (q % 12) * 4;
        float eyh = ey[h];
        float d0 = ex[w + 0] * eyh - t2.x;
        float d1 = ex[w + 1] * eyh - t2.y;
        float d2 = ex[w + 2] * eyh - t2.z;
        float d3 = ex[w + 3] * eyh - t2.w;
        sum += d0 * d0 + d1 * d1 + d2 * d2 + d3 * d3;
    }
    sum *= coef;

    // Warp reduce
#pragma unroll
    for (int off = 16; off > 0; off >>= 1)
        sum += __shfl_down_sync(0xFFFFFFFFu, sum, off);
    if ((tid & 31) == 0) s_warp[tid >> 5] = sum;
    __syncthreads();

    if (tid < 8) {
        float v = s_warp[tid];
#pragma unroll
        for (int off = 4; off > 0; off >>= 1)
            v += __shfl_down_sync(0x000000FFu, v, off);
        if (tid == 0) {
            atomicAdd(&g_acc, (double)v);
            __threadfence();
            unsigned int ticket = atomicAdd(&g_cnt, 1u);
            if (ticket == NK - 1) {
                // All NK blocks' g_acc contributions are globally visible.
                double total = atomicAdd(&g_acc, 0.0);   // coherent L2 read
                out[0] = (float)(total / TOTAL);         // LOSS_WEIGHT = 1.0
                // Reset for the next graph replay (no other block is running).
                g_acc = 0.0;
                g_cnt = 0u;
            }
        }
    }
}

extern "C" void kernel_launch(void* const* d_in, const int* in_sizes, int n_in,
                              void* d_out, int out_size) {
    const float* pred    = (const float*)d_in[0];
    const float* sigma   = (const float*)d_in[1];
    const float* teacher = (const float*)d_in[2];
    const float* twgt    = (const float*)d_in[3];
    float* out = (float*)d_out;

    reg2hm_loss_kernel<<<NK, 256>>>(pred, sigma, teacher, twgt, out);
}

// round 6
// speedup vs baseline: 1.0769x; 1.0769x over previous
#include <cuda_runtime.h>

// Problem constants
#define NN 512
#define KK 17
#define WW 48
#define HH 64
#define NK (NN * KK)                       // 8704
#define HMSZ (HH * WW)                     // 3072
#define TOTAL ((double)NN * KK * HH * WW)  // 26738688
#define GRID 592                           // 4 blocks/SM on 148 SMs, single wave

__device__ double g_acc;          // zero-initialized; reset by last block each run
__device__ unsigned int g_cnt;    // ditto

__global__ __launch_bounds__(256) void reg2hm_loss_kernel(
    const float* __restrict__ pred,      // [N,K,2]
    const float* __restrict__ sigma,     // [N,K,2]
    const float* __restrict__ teacher,   // [N,K,H,W]
    const float* __restrict__ twgt,      // [N,K,1]
    float* __restrict__ out)             // [1]
{
    const int tid = threadIdx.x;

    __shared__ float ex[2][WW];
    __shared__ float ey[2][HH];
    __shared__ float s_warp[8];

    // Precompute this thread's (h, w) coordinates for its 3 quads.
    const int q0 = tid,        h0 = q0 / 12, w0 = (q0 % 12) * 4;
    const int q1 = tid + 256,  h1 = q1 / 12, w1 = (q1 % 12) * 4;
    const int q2 = tid + 512,  h2 = q2 / 12, w2 = (q2 % 12) * 4;

    int nk = blockIdx.x;

    // ---- Prologue: loads + exp table for iteration 0 ----
    const float4* tp = reinterpret_cast<const float4*>(teacher + (size_t)nk * HMSZ);
    float4 t0 = tp[q0], t1 = tp[q1], t2 = tp[q2];

    float coef;
    {
        float mux = pred[nk * 2 + 0] * (float)WW;
        float muy = pred[nk * 2 + 1] * (float)HH;
        float sx  = sigma[nk * 2 + 0];
        float sy  = sigma[nk * 2 + 1];
        float m = ((mux - 3.0f * sx < (float)WW) &&
                   (muy - 3.0f * sy < (float)HH) &&
                   (mux + 3.0f * sx + 1.0f >= 0.0f) &&
                   (muy + 3.0f * sy + 1.0f >= 0.0f)) ? 1.0f : 0.0f;
        float tw = twgt[nk] * m;
        coef = tw * tw;
        float invx = 1.0f / (sx * sx + 1e-9f);
        float invy = 1.0f / (sy * sy + 1e-9f);
        if (tid < WW) {
            float d = (float)tid - mux;
            ex[0][tid] = __expf(-0.5f * d * d * invx);
        } else if (tid >= 64 && tid < 64 + HH) {
            int h = tid - 64;
            float d = (float)h - muy;
            ey[0][h] = __expf(-0.5f * d * d * invy);
        }
    }

    float acc = 0.0f;
    int buf = 0;

    while (true) {
        const int nk2 = nk + GRID;
        const bool has_next = (nk2 < NK);

        // ---- Issue next iteration's loads FIRST (front-batched MLP) ----
        float4 u0, u1, u2;
        float nmux = 0.f, nmuy = 0.f, nsx = 1.f, nsy = 1.f, ntw = 0.f;
        if (has_next) {
            const float4* tq = reinterpret_cast<const float4*>(teacher + (size_t)nk2 * HMSZ);
            u0 = tq[q0]; u1 = tq[q1]; u2 = tq[q2];
            nmux = pred[nk2 * 2 + 0] * (float)WW;
            nmuy = pred[nk2 * 2 + 1] * (float)HH;
            nsx  = sigma[nk2 * 2 + 0];
            nsy  = sigma[nk2 * 2 + 1];
            ntw  = twgt[nk2];
        }

        __syncthreads();   // ex/ey[buf] now visible

        // ---- Heavy sum for current heatmap (loads arrived last iteration) ----
        {
            float ey0 = ey[buf][h0], ey1 = ey[buf][h1], ey2 = ey[buf][h2];
            float d0 = ex[buf][w0 + 0] * ey0 - t0.x;
            float d1 = ex[buf][w0 + 1] * ey0 - t0.y;
            float d2 = ex[buf][w0 + 2] * ey0 - t0.z;
            float d3 = ex[buf][w0 + 3] * ey0 - t0.w;
            float s  = d0 * d0 + d1 * d1 + d2 * d2 + d3 * d3;
            d0 = ex[buf][w1 + 0] * ey1 - t1.x;
            d1 = ex[buf][w1 + 1] * ey1 - t1.y;
            d2 = ex[buf][w1 + 2] * ey1 - t1.z;
            d3 = ex[buf][w1 + 3] * ey1 - t1.w;
            s += d0 * d0 + d1 * d1 + d2 * d2 + d3 * d3;
            d0 = ex[buf][w2 + 0] * ey2 - t2.x;
            d1 = ex[buf][w2 + 1] * ey2 - t2.y;
            d2 = ex[buf][w2 + 2] * ey2 - t2.z;
            d3 = ex[buf][w2 + 3] * ey2 - t2.w;
            s += d0 * d0 + d1 * d1 + d2 * d2 + d3 * d3;
            acc += s * coef;
        }

        if (!has_next) break;

        // ---- Build next iteration's exp tables (params arrived during sum) ----
        {
            float m = ((nmux - 3.0f * nsx < (float)WW) &&
                       (nmuy - 3.0f * nsy < (float)HH) &&
                       (nmux + 3.0f * nsx + 1.0f >= 0.0f) &&
                       (nmuy + 3.0f * nsy + 1.0f >= 0.0f)) ? 1.0f : 0.0f;
            float tw = ntw * m;
            coef = tw * tw;
            float invx = 1.0f / (nsx * nsx + 1e-9f);
            float invy = 1.0f / (nsy * nsy + 1e-9f);
            int nb = buf ^ 1;
            if (tid < WW) {
                float d = (float)tid - nmux;
                ex[nb][tid] = __expf(-0.5f * d * d * invx);
            } else if (tid >= 64 && tid < 64 + HH) {
                int h = tid - 64;
                float d = (float)h - nmuy;
                ey[nb][h] = __expf(-0.5f * d * d * invy);
            }
        }

        t0 = u0; t1 = u1; t2 = u2;
        buf ^= 1;
        nk = nk2;
    }

    // ---- Block reduce (once per block) ----
#pragma unroll
    for (int off = 16; off > 0; off >>= 1)
        acc += __shfl_down_sync(0xFFFFFFFFu, acc, off);
    if ((tid & 31) == 0) s_warp[tid >> 5] = acc;
    __syncthreads();

    if (tid < 8) {
        float v = s_warp[tid];
#pragma unroll
        for (int off = 4; off > 0; off >>= 1)
            v += __shfl_down_sync(0x000000FFu, v, off);
        if (tid == 0) {
            atomicAdd(&g_acc, (double)v);
            __threadfence();
            unsigned int ticket = atomicAdd(&g_cnt, 1u);
            if (ticket == GRID - 1) {
                double total = atomicAdd(&g_acc, 0.0);   // coherent read
                out[0] = (float)(total / TOTAL);         // LOSS_WEIGHT = 1.0
                g_acc = 0.0;                             // reset for next replay
                g_cnt = 0u;
            }
        }
    }
}

extern "C" void kernel_launch(void* const* d_in, const int* in_sizes, int n_in,
                              void* d_out, int out_size) {
    const float* pred    = (const float*)d_in[0];
    const float* sigma   = (const float*)d_in[1];
    const float* teacher = (const float*)d_in[2];
    const float* twgt    = (const float*)d_in[3];
    float* out = (float*)d_out;

    reg2hm_loss_kernel<<<GRID, 256>>>(pred, sigma, teacher, twgt, out);
}

// round 7
// speedup vs baseline: 1.0784x; 1.0014x over previous
#include <cuda_runtime.h>

// Problem constants
#define NN 512
#define KK 17
#define WW 48
#define HH 64
#define NK (NN * KK)                       // 8704
#define HMSZ (HH * WW)                     // 3072
#define TOTAL ((double)NN * KK * HH * WW)  // 26738688
#define GRID 592                           // 4 blocks/SM on 148 SMs, single wave

__device__ double g_acc;          // zero-initialized; reset by last block each run
__device__ unsigned int g_cnt;    // ditto

__global__ __launch_bounds__(256, 4) void reg2hm_loss_kernel(
    const float* __restrict__ pred,      // [N,K,2]
    const float* __restrict__ sigma,     // [N,K,2]
    const float* __restrict__ teacher,   // [N,K,H,W]
    const float* __restrict__ twgt,      // [N,K,1]
    float* __restrict__ out)             // [1]
{
    const int tid = threadIdx.x;

    __shared__ __align__(16) float ex[2][WW];   // read as float4[12]
    __shared__ float ey[2][HH];
    __shared__ float s_warp[8];

    // Thread-fixed coordinates for its 3 quads (12 float4 per row, W=48).
    const int q0 = tid,        h0 = q0 / 12, c0 = q0 % 12;
    const int q1 = tid + 256,  h1 = q1 / 12, c1 = q1 % 12;
    const int q2 = tid + 512,  h2 = q2 / 12, c2 = q2 % 12;

    int nk = blockIdx.x;

    // ---- Pipeline registers ----
    float4 t0, t1, t2;                 // data for nk       (compute this iter)
    float4 u0, u1, u2;                 // data for nk+G     (arriving)
    float nmux, nmuy, nsx, nsy, ntw;   // params for nk+G
    float coef;                        // weight for nk

    // ---- Prologue ----
    {
        const float4* tp = reinterpret_cast<const float4*>(teacher + (size_t)nk * HMSZ);
        t0 = tp[q0]; t1 = tp[q1]; t2 = tp[q2];

        if (nk + GRID < NK) {
            const float4* tq = reinterpret_cast<const float4*>(teacher + (size_t)(nk + GRID) * HMSZ);
            u0 = tq[q0]; u1 = tq[q1]; u2 = tq[q2];
            nmux = pred[(nk + GRID) * 2 + 0] * (float)WW;
            nmuy = pred[(nk + GRID) * 2 + 1] * (float)HH;
            nsx  = sigma[(nk + GRID) * 2 + 0];
            nsy  = sigma[(nk + GRID) * 2 + 1];
            ntw  = twgt[nk + GRID];
        } else {
            u0 = u1 = u2 = make_float4(0.f, 0.f, 0.f, 0.f);
            nmux = nmuy = 0.f; nsx = nsy = 1.f; ntw = 0.f;
        }

        // Params + exp table for iteration 0
        float mux = pred[nk * 2 + 0] * (float)WW;
        float muy = pred[nk * 2 + 1] * (float)HH;
        float sx  = sigma[nk * 2 + 0];
        float sy  = sigma[nk * 2 + 1];
        float m = ((mux - 3.0f * sx < (float)WW) &&
                   (muy - 3.0f * sy < (float)HH) &&
                   (mux + 3.0f * sx + 1.0f >= 0.0f) &&
                   (muy + 3.0f * sy + 1.0f >= 0.0f)) ? 1.0f : 0.0f;
        float tw = twgt[nk] * m;
        coef = tw * tw;
        float invx = 1.0f / (sx * sx + 1e-9f);
        float invy = 1.0f / (sy * sy + 1e-9f);
        if (tid < WW) {
            float d = (float)tid - mux;
            ex[0][tid] = __expf(-0.5f * d * d * invx);
        } else if (tid >= 64 && tid < 64 + HH) {
            int h = tid - 64;
            float d = (float)h - muy;
            ey[0][h] = __expf(-0.5f * d * d * invy);
        }
    }

    float acc = 0.0f;
    int buf = 0;

    while (true) {
        const bool has1 = (nk + GRID)     < NK;
        const bool has2 = (nk + 2 * GRID) < NK;

        // ---- Issue loads for nk+2G FIRST (front-batched, consumed in 2 iters) ----
        float4 v0, v1, v2;
        float pmux = 0.f, pmuy = 0.f, psx = 1.f, psy = 1.f, ptw = 0.f;
        if (has2) {
            const int nk2 = nk + 2 * GRID;
            const float4* tq = reinterpret_cast<const float4*>(teacher + (size_t)nk2 * HMSZ);
            v0 = tq[q0]; v1 = tq[q1]; v2 = tq[q2];
            pmux = pred[nk2 * 2 + 0] * (float)WW;
            pmuy = pred[nk2 * 2 + 1] * (float)HH;
            psx  = sigma[nk2 * 2 + 0];
            psy  = sigma[nk2 * 2 + 1];
            ptw  = twgt[nk2];
        } else {
            v0 = v1 = v2 = make_float4(0.f, 0.f, 0.f, 0.f);
        }

        __syncthreads();   // table[buf] visible; table[buf^1] reads (iter-1) done

        // ---- Heavy sum for current heatmap (t* arrived 2 iterations ago) ----
        {
            const float4* ex4 = reinterpret_cast<const float4*>(ex[buf]);
            float  ey0 = ey[buf][h0], ey1 = ey[buf][h1], ey2 = ey[buf][h2];
            float4 e0 = ex4[c0], e1 = ex4[c1], e2 = ex4[c2];

            float d0 = e0.x * ey0 - t0.x;
            float d1 = e0.y * ey0 - t0.y;
            float d2 = e0.z * ey0 - t0.z;
            float d3 = e0.w * ey0 - t0.w;
            float s  = d0 * d0 + d1 * d1 + d2 * d2 + d3 * d3;
            d0 = e1.x * ey1 - t1.x;
            d1 = e1.y * ey1 - t1.y;
            d2 = e1.z * ey1 - t1.z;
            d3 = e1.w * ey1 - t1.w;
            s += d0 * d0 + d1 * d1 + d2 * d2 + d3 * d3;
            d0 = e2.x * ey2 - t2.x;
            d1 = e2.y * ey2 - t2.y;
            d2 = e2.z * ey2 - t2.z;
            d3 = e2.w * ey2 - t2.w;
            s += d0 * d0 + d1 * d1 + d2 * d2 + d3 * d3;
            acc += s * coef;
        }

        if (!has1) break;

        // ---- Build table for nk+G from n-params (loaded 2 iterations ago) ----
        {
            float m = ((nmux - 3.0f * nsx < (float)WW) &&
                       (nmuy - 3.0f * nsy < (float)HH) &&
                       (nmux + 3.0f * nsx + 1.0f >= 0.0f) &&
                       (nmuy + 3.0f * nsy + 1.0f >= 0.0f)) ? 1.0f : 0.0f;
            float tw = ntw * m;
            coef = tw * tw;
            float invx = 1.0f / (nsx * nsx + 1e-9f);
            float invy = 1.0f / (nsy * nsy + 1e-9f);
            int nb = buf ^ 1;
            if (tid < WW) {
                float d = (float)tid - nmux;
                ex[nb][tid] = __expf(-0.5f * d * d * invx);
            } else if (tid >= 64 && tid < 64 + HH) {
                int h = tid - 64;
                float d = (float)h - nmuy;
                ey[nb][h] = __expf(-0.5f * d * d * invy);
            }
        }

        // ---- Shift pipeline ----
        t0 = u0; t1 = u1; t2 = u2;
        u0 = v0; u1 = v1; u2 = v2;
        nmux = pmux; nmuy = pmuy; nsx = psx; nsy = psy; ntw = ptw;
        buf ^= 1;
        nk += GRID;
    }

    // ---- Block reduce (once per block) ----
#pragma unroll
    for (int off = 16; off > 0; off >>= 1)
        acc += __shfl_down_sync(0xFFFFFFFFu, acc, off);
    if ((tid & 31) == 0) s_warp[tid >> 5] = acc;
    __syncthreads();

    if (tid < 8) {
        float v = s_warp[tid];
#pragma unroll
        for (int off = 4; off > 0; off >>= 1)
            v += __shfl_down_sync(0x000000FFu, v, off);
        if (tid == 0) {
            atomicAdd(&g_acc, (double)v);
            __threadfence();
            unsigned int ticket = atomicAdd(&g_cnt, 1u);
            if (ticket == GRID - 1) {
                double total = atomicAdd(&g_acc, 0.0);   // coherent read
                out[0] = (float)(total / TOTAL);         // LOSS_WEIGHT = 1.0
                g_acc = 0.0;                             // reset for next replay
                g_cnt = 0u;
            }
        }
    }
}

extern "C" void kernel_launch(void* const* d_in, const int* in_sizes, int n_in,
                              void* d_out, int out_size) {
    const float* pred    = (const float*)d_in[0];
    const float* sigma   = (const float*)d_in[1];
    const float* teacher = (const float*)d_in[2];
    const float* twgt    = (const float*)d_in[3];
    float* out = (float*)d_out;

    reg2hm_loss_kernel<<<GRID, 256>>>(pred, sigma, teacher, twgt, out);
}